// round 10
// baseline (speedup 1.0000x reference)
#include <cuda_runtime.h>
#include <cuda_bf16.h>
#include <cstdint>

#define Tt 512
#define Hh 512
#define Ff 256
#define Bb 256
#define NCTA 128
#define TPB  256

// ---------------- main-kernel smem layout ----------------
#define WSTR_E 520
#define WSTR_B 1040
#define WHI_OFF 0
#define WLO_OFF (32 * WSTR_B)              // 33280
#define A_OFF   (2 * 32 * WSTR_B)          // 66560
#define SA_STR  144
#define CHUNKB  (32 * SA_STR)              // 4608
#define A_BYTES (16 * CHUNKB)              // 73728 (16 h chunks)
#define XP_OFF  (A_OFF + A_BYTES)          // 140288
#define XPSLOT  4608
#define RED_OFF (XP_OFF + 2 * XPSLOT)      // 149504
#define MB_OFF  (RED_OFF + 4096)           // 153600
#define SM_DYN  (MB_OFF + 64)              // 153664

// ---------------- prekernel smem layout ----------------
#define PKWSTR_E 264
#define PKWSTR_B 528
#define PWHI_OFF 0
#define PWLO_OFF (32 * PKWSTR_B)           // 16896
#define PX_OFF   (2 * 32 * PKWSTR_B)       // 33792
#define TILEB    (128 * SA_STR)            // 18432
#define PK_SMEM  (PX_OFF + 8 * TILEB)      // 181248

__device__ __align__(1024) __nv_bfloat16 g_xhi[(size_t)Bb * Tt * Ff];
__device__ __align__(1024) __nv_bfloat16 g_xlo[(size_t)Bb * Tt * Ff];
__device__ __align__(1024) float         g_xp [(size_t)Bb * Tt * Hh];   // 268MB
__device__ __align__(1024) __nv_bfloat16 g_hhi[2][Bb * Hh];
__device__ __align__(1024) __nv_bfloat16 g_hlo[2][Bb * Hh];
__device__ unsigned g_pflag[8 * 16 * 16];  // [mq][nq] producer flags, 64B apart
__device__ unsigned g_exit;

// ---------------- helpers ----------------
__device__ __forceinline__ uint32_t smem_u32(const void* p) {
    uint32_t a;
    asm("{ .reg .u64 t; cvta.to.shared.u64 t, %1; cvt.u32.u64 %0, t; }" : "=r"(a) : "l"(p));
    return a;
}
__device__ __forceinline__ void cp_async16(uint32_t dst, const void* src) {
    asm volatile("cp.async.cg.shared.global [%0], [%1], 16;" :: "r"(dst), "l"(src) : "memory");
}
__device__ __forceinline__ void cp_commit() {
    asm volatile("cp.async.commit_group;" ::: "memory");
}
__device__ __forceinline__ void wait_groups(int k) {
    switch (k) {
        case 0: asm volatile("cp.async.wait_group 0;" ::: "memory"); break;
        case 1: asm volatile("cp.async.wait_group 1;" ::: "memory"); break;
        case 2: asm volatile("cp.async.wait_group 2;" ::: "memory"); break;
        default: asm volatile("cp.async.wait_group 3;" ::: "memory"); break;
    }
}
__device__ __forceinline__ void mbar_init(uint32_t a, uint32_t c) {
    asm volatile("mbarrier.init.shared.b64 [%0], %1;" :: "r"(a), "r"(c) : "memory");
}
__device__ __forceinline__ void cpa_arrive(uint32_t a) {
    asm volatile("cp.async.mbarrier.arrive.noinc.shared.b64 [%0];" :: "r"(a) : "memory");
}
__device__ __forceinline__ void mbar_wait(uint32_t a, uint32_t par) {
    uint32_t done;
    do {
        asm volatile("{\n\t.reg .pred p;\n\t"
                     "mbarrier.try_wait.parity.shared::cta.b64 p, [%1], %2, 0x989680;\n\t"
                     "selp.b32 %0, 1, 0, p;\n\t}"
                     : "=r"(done) : "r"(a), "r"(par) : "memory");
    } while (!done);
}
__device__ __forceinline__ void ldm_x4(uint32_t& r0, uint32_t& r1, uint32_t& r2, uint32_t& r3,
                                       uint32_t addr) {
    asm volatile("ldmatrix.sync.aligned.m8n8.x4.shared.b16 {%0,%1,%2,%3}, [%4];"
                 : "=r"(r0), "=r"(r1), "=r"(r2), "=r"(r3) : "r"(addr));
}
__device__ __forceinline__ void mma16816(float* d, const uint32_t* a, uint32_t b0, uint32_t b1) {
    asm volatile("mma.sync.aligned.m16n8k16.row.col.f32.bf16.bf16.f32 "
                 "{%0,%1,%2,%3}, {%4,%5,%6,%7}, {%8,%9}, {%0,%1,%2,%3};"
                 : "+f"(d[0]), "+f"(d[1]), "+f"(d[2]), "+f"(d[3])
                 : "r"(a[0]), "r"(a[1]), "r"(a[2]), "r"(a[3]), "r"(b0), "r"(b1));
}
__device__ __forceinline__ uint32_t packbf(__nv_bfloat16 a, __nv_bfloat16 b) {
    return (uint32_t)__bfloat16_as_ushort(a) | ((uint32_t)__bfloat16_as_ushort(b) << 16);
}
__device__ __forceinline__ void stcg32(void* p, uint32_t v) {
    asm volatile("st.global.cg.b32 [%0], %1;" :: "l"(p), "r"(v) : "memory");
}
__device__ __forceinline__ float tanh_acc(float x) {
    float e = __expf(2.f * x);
    return 1.f - 2.f / (e + 1.f);
}

// ---------------- prep: split x into bf16 hi/lo ----------------
__global__ void xsplit(const float* __restrict__ x) {
    size_t base = ((size_t)blockIdx.x * 256 + threadIdx.x) * 8;
    float4 v0 = __ldg((const float4*)(x + base));
    float4 v1 = __ldg((const float4*)(x + base) + 1);
    float v[8] = {v0.x, v0.y, v0.z, v0.w, v1.x, v1.y, v1.z, v1.w};
    uint32_t ph[4], pl[4];
    #pragma unroll
    for (int j = 0; j < 4; j++) {
        __nv_bfloat16 h0 = __float2bfloat16(v[2*j]);
        __nv_bfloat16 h1 = __float2bfloat16(v[2*j+1]);
        __nv_bfloat16 l0 = __float2bfloat16(v[2*j]   - __bfloat162float(h0));
        __nv_bfloat16 l1 = __float2bfloat16(v[2*j+1] - __bfloat162float(h1));
        ph[j] = packbf(h0, h1); pl[j] = packbf(l0, l1);
    }
    *(uint4*)&g_xhi[base] = make_uint4(ph[0], ph[1], ph[2], ph[3]);
    *(uint4*)&g_xlo[base] = make_uint4(pl[0], pl[1], pl[2], pl[3]);
}

// ---------------- prekernel: xp = x @ Wx (3-term bf16 split, fp32 out) ----------------
__global__ void __launch_bounds__(256, 1)
xproj(const float* __restrict__ Wx)
{
    extern __shared__ char sm[];
    const uint32_t s0 = smem_u32(sm);
    const int tid = threadIdx.x, wid = tid >> 5, lane = tid & 31;
    const int nq = blockIdx.x & 15, mb = blockIdx.x >> 4;
    const int qn = nq * 32;

    // W slice: [n<32][k<256] hi+lo
    __nv_bfloat16* pWhi = (__nv_bfloat16*)(sm + PWHI_OFF);
    __nv_bfloat16* pWlo = (__nv_bfloat16*)(sm + PWLO_OFF);
    for (int idx = tid; idx < 8192; idx += 256) {
        int n = idx >> 8, k = idx & 255;
        float w = Wx[k * Hh + qn + n];
        __nv_bfloat16 hi = __float2bfloat16(w);
        pWhi[n * PKWSTR_E + k] = hi;
        pWlo[n * PKWSTR_E + k] = __float2bfloat16(w - __bfloat162float(hi));
    }

    // issue all 4 k-pairs (x_hi + x_lo tiles), 4 commit groups
    {
        const int row = tid >> 1;
        const int sb  = (tid & 1) * 64;
        #pragma unroll
        for (int c = 0; c < 4; c++) {
            size_t gr = ((size_t)(mb * 128 + row)) * 256 + c * 64;
            uint32_t dhi = s0 + PX_OFF + (uint32_t)c * (2 * TILEB) + (uint32_t)row * SA_STR + sb;
            const char* shi = (const char*)(g_xhi + gr) + sb;
            const char* slo = (const char*)(g_xlo + gr) + sb;
            #pragma unroll
            for (int j = 0; j < 4; j++) cp_async16(dhi + j * 16, shi + j * 16);
            #pragma unroll
            for (int j = 0; j < 4; j++) cp_async16(dhi + TILEB + j * 16, slo + j * 16);
            cp_commit();
        }
    }
    __syncthreads();   // W visible

    const uint32_t aoff = (uint32_t)(wid * 16 + (lane & 15)) * SA_STR + ((lane >> 4) << 4);
    const uint32_t boff = (uint32_t)(((lane >> 4) << 3) + (lane & 7)) * PKWSTR_B
                        + (((lane >> 3) & 1) << 4);
    const uint32_t bHi = s0 + PWHI_OFF + boff;
    const uint32_t bLo = s0 + PWLO_OFF + boff;

    float D0[4] = {0,0,0,0}, D1[4] = {0,0,0,0}, D2[4] = {0,0,0,0}, D3[4] = {0,0,0,0};

    for (int c = 0; c < 4; c++) {
        wait_groups(3 - c);
        __syncthreads();
        const uint32_t ahB = s0 + PX_OFF + (uint32_t)c * (2 * TILEB) + aoff;
        #pragma unroll
        for (int k16 = 0; k16 < 4; k16++) {
            const uint32_t kb = (uint32_t)c * 128 + k16 * 32;
            uint32_t ah[4], al[4], b0, b1, b2, b3;
            ldm_x4(ah[0], ah[1], ah[2], ah[3], ahB + k16 * 32);
            ldm_x4(al[0], al[1], al[2], al[3], ahB + TILEB + k16 * 32);
            // cols 0-15
            ldm_x4(b0, b1, b2, b3, bHi + kb);
            mma16816(D0, ah, b0, b1); mma16816(D1, ah, b2, b3);
            mma16816(D0, al, b0, b1); mma16816(D1, al, b2, b3);
            ldm_x4(b0, b1, b2, b3, bLo + kb);
            mma16816(D0, ah, b0, b1); mma16816(D1, ah, b2, b3);
            // cols 16-31
            ldm_x4(b0, b1, b2, b3, bHi + 16 * PKWSTR_B + kb);
            mma16816(D2, ah, b0, b1); mma16816(D3, ah, b2, b3);
            mma16816(D2, al, b0, b1); mma16816(D3, al, b2, b3);
            ldm_x4(b0, b1, b2, b3, bLo + 16 * PKWSTR_B + kb);
            mma16816(D2, ah, b0, b1); mma16816(D3, ah, b2, b3);
        }
    }

    // write xp
    const size_t r0 = (size_t)(mb * 128 + wid * 16 + (lane >> 2));
    const int cb = qn + (lane & 3) * 2;
    float* o0 = g_xp + r0 * Hh + cb;
    float* o1 = g_xp + (r0 + 8) * Hh + cb;
    *(float2*)(o0)      = make_float2(D0[0], D0[1]);
    *(float2*)(o1)      = make_float2(D0[2], D0[3]);
    *(float2*)(o0 + 8)  = make_float2(D1[0], D1[1]);
    *(float2*)(o1 + 8)  = make_float2(D1[2], D1[3]);
    *(float2*)(o0 + 16) = make_float2(D2[0], D2[1]);
    *(float2*)(o1 + 16) = make_float2(D2[2], D2[3]);
    *(float2*)(o0 + 24) = make_float2(D3[0], D3[1]);
    *(float2*)(o1 + 24) = make_float2(D3[2], D3[3]);
}

// ---------------- main-kernel chunk compute ----------------
// chunk ids: 0-7 h_hi, 8-15 h_lo
__device__ __forceinline__ void compute_chunk(bool hi, int c, uint32_t aBase,
                                              uint32_t bHi, uint32_t bLo,
                                              float* D0a, float* D0b,
                                              float* D1a, float* D1b) {
    const uint32_t kg2 = (uint32_t)(c & 7) * 128;
    const uint32_t ab = aBase + (uint32_t)c * CHUNKB;
    #pragma unroll
    for (int k16 = 0; k16 < 4; k16++) {
        float* P0 = (k16 & 1) ? D0b : D0a;
        float* P1 = (k16 & 1) ? D1b : D1a;
        uint32_t a[4], b0, b1, b2, b3;
        ldm_x4(a[0], a[1], a[2], a[3], ab + k16 * 32);
        ldm_x4(b0, b1, b2, b3, bHi + kg2 + k16 * 32);
        mma16816(P0, a, b0, b1);
        mma16816(P1, a, b2, b3);
        if (hi) {
            ldm_x4(b0, b1, b2, b3, bLo + kg2 + k16 * 32);
            mma16816(P0, a, b0, b1);
            mma16816(P1, a, b2, b3);
        }
    }
}

// ---------------- persistent HMMA recurrence (h only; xp precomputed) ----------------
__global__ void __launch_bounds__(TPB, 1)
rnn_mma(const float* __restrict__ Wh, const float* __restrict__ bias,
        const float* __restrict__ Wfc, const float* __restrict__ bfc,
        float* __restrict__ out)
{
    extern __shared__ char sm[];
    const uint32_t s0 = smem_u32(sm);

    const int tid  = threadIdx.x;
    const int wid  = tid >> 5, lane = tid & 31;
    const int grp  = wid >> 2;
    const int qw   = wid & 3;
    const int mq   = blockIdx.x >> 4;
    const int nq   = blockIdx.x & 15;
    const int mbase = mq * 32, qn = nq * 32;
    const int m_off = (qw >> 1) * 16;
    const int n_off = (qw & 1) * 16;

    unsigned* myflag = &g_pflag[(mq * 16 + nq) * 16];
    unsigned* grpflags = &g_pflag[mq * 16 * 16];

    const uint32_t MBQ = s0 + MB_OFF;       // 4 quad mbarriers
    const uint32_t MBX = s0 + MB_OFF + 32;  // xp mbarrier

    if (tid == 0) {
        #pragma unroll
        for (int i = 0; i < 4; i++) mbar_init(MBQ + 8 * i, TPB);
        mbar_init(MBX, TPB);
    }

    // resident Wh split slice: [n<32][k<512]
    __nv_bfloat16* sWhi = (__nv_bfloat16*)(sm + WHI_OFF);
    __nv_bfloat16* sWlo = (__nv_bfloat16*)(sm + WLO_OFF);
    for (int idx = tid; idx < 32 * 512; idx += TPB) {
        int n = idx >> 9, k = idx & 511;
        float w = Wh[k * Hh + qn + n];
        __nv_bfloat16 hi = __float2bfloat16(w);
        sWhi[n * WSTR_E + k] = hi;
        sWlo[n * WSTR_E + k] = __float2bfloat16(w - __bfloat162float(hi));
    }
    __syncthreads();

    const uint32_t aoff = (uint32_t)(m_off + (lane & 15)) * SA_STR + ((lane >> 4) << 4);
    const uint32_t boff = (uint32_t)(n_off + ((lane >> 4) << 3) + (lane & 7)) * WSTR_B
                        + (((lane >> 3) & 1) << 4);
    const uint32_t aBase = s0 + A_OFF + aoff;
    const uint32_t bHi   = s0 + WHI_OFF + boff;
    const uint32_t bLo   = s0 + WLO_OFF + boff;

    const int irow = tid >> 3;
    const int iseg = tid & 7;
    const uint32_t pdst0 = s0 + A_OFF + (uint32_t)irow * SA_STR + (uint32_t)iseg * 16;
    const uint32_t xdst0 = s0 + XP_OFF + (uint32_t)irow * SA_STR + (uint32_t)iseg * 16;

    float* red = (float*)(sm + RED_OFF);

    const int c0 = qn + n_off + (lane & 3) * 2;
    const float bb0 = bias[c0],     bb1 = bias[c0 + 1];
    const float bb8 = bias[c0 + 8], bb9 = bias[c0 + 9];
    const int erow0 = mbase + m_off + (lane >> 2);
    const int lr0 = m_off + (lane >> 2);
    const int lc0 = n_off + (lane & 3) * 2;

    for (int t = 0; t < Tt; ++t) {
        // xp tile for this step (depends only on t) -> slot t&1
        {
            const float* src = g_xp + ((size_t)(mbase + irow) * Tt + t) * Hh + qn + iseg * 4;
            cp_async16(xdst0 + (uint32_t)(t & 1) * XPSLOT, src);
            cpa_arrive(MBX);
        }

        float D0a[4] = {0,0,0,0}, D0b[4] = {0,0,0,0};
        float D1a[4] = {0,0,0,0}, D1b[4] = {0,0,0,0};

        if (t) {
            // poll all 16 producer flags in parallel
            if (tid < 16) {
                while (*(volatile unsigned*)&grpflags[tid * 16] < (unsigned)t) { }
            }
            __syncthreads();
            // issue 4 quads: {hi 2q, hi 2q+1, lo 8+2q, lo 9+2q}
            #pragma unroll
            for (int q = 0; q < 4; q++) {
                const __nv_bfloat16* hh = g_hhi[t & 1] + (size_t)(mbase + irow) * Hh;
                const __nv_bfloat16* hl = g_hlo[t & 1] + (size_t)(mbase + irow) * Hh;
                cp_async16(pdst0 + (uint32_t)(2*q)     * CHUNKB, (const char*)(hh + (2*q)   * 64) + iseg * 16);
                cp_async16(pdst0 + (uint32_t)(2*q + 1) * CHUNKB, (const char*)(hh + (2*q+1) * 64) + iseg * 16);
                cp_async16(pdst0 + (uint32_t)(8 + 2*q) * CHUNKB, (const char*)(hl + (2*q)   * 64) + iseg * 16);
                cp_async16(pdst0 + (uint32_t)(9 + 2*q) * CHUNKB, (const char*)(hl + (2*q+1) * 64) + iseg * 16);
                cpa_arrive(MBQ + 8 * q);
            }
            // drain quads
            #pragma unroll
            for (int q = 0; q < 4; q++) {
                mbar_wait(MBQ + 8 * q, (t - 1) & 1);
                compute_chunk(true,  2*q + grp,     aBase, bHi, bLo, D0a, D0b, D1a, D1b);
                compute_chunk(false, 8 + 2*q + grp, aBase, bHi, bLo, D0a, D0b, D1a, D1b);
            }
        }

        // cross-group reduction
        if (grp == 1) {
            float* rp = red + ((qw * 32 + lane) << 3);
            rp[0] = D0a[0] + D0b[0]; rp[1] = D0a[1] + D0b[1];
            rp[2] = D0a[2] + D0b[2]; rp[3] = D0a[3] + D0b[3];
            rp[4] = D1a[0] + D1b[0]; rp[5] = D1a[1] + D1b[1];
            rp[6] = D1a[2] + D1b[2]; rp[7] = D1a[3] + D1b[3];
        }
        __syncthreads();

        mbar_wait(MBX, t & 1);   // xp tile resident

        if (grp == 0) {
            const float* rp = red + ((qw * 32 + lane) << 3);
            const float* xps = (const float*)(sm + XP_OFF + (t & 1) * XPSLOT);
            float2 x00 = *(const float2*)&xps[lr0 * 36 + lc0];
            float2 x01 = *(const float2*)&xps[lr0 * 36 + lc0 + 8];
            float2 x10 = *(const float2*)&xps[(lr0 + 8) * 36 + lc0];
            float2 x11 = *(const float2*)&xps[(lr0 + 8) * 36 + lc0 + 8];

            float v00 = D0a[0] + D0b[0] + rp[0] + x00.x, v01 = D0a[1] + D0b[1] + rp[1] + x00.y;
            float v02 = D0a[2] + D0b[2] + rp[2] + x10.x, v03 = D0a[3] + D0b[3] + rp[3] + x10.y;
            float v10 = D1a[0] + D1b[0] + rp[4] + x01.x, v11 = D1a[1] + D1b[1] + rp[5] + x01.y;
            float v12 = D1a[2] + D1b[2] + rp[6] + x11.x, v13 = D1a[3] + D1b[3] + rp[7] + x11.y;

            float h00 = tanh_acc(v00 + bb0), h01 = tanh_acc(v01 + bb1);
            float h10 = tanh_acc(v02 + bb0), h11 = tanh_acc(v03 + bb1);
            float g00 = tanh_acc(v10 + bb8), g01 = tanh_acc(v11 + bb9);
            float g10 = tanh_acc(v12 + bb8), g11 = tanh_acc(v13 + bb9);

            const int nxt = (t & 1) ^ 1;
            __nv_bfloat16* dhi = g_hhi[nxt];
            __nv_bfloat16* dlo = g_hlo[nxt];
            size_t o0 = (size_t)erow0 * Hh + c0;
            size_t o1 = (size_t)(erow0 + 8) * Hh + c0;
            #define EMIT(off, va, vb) do {                                              \
                __nv_bfloat16 _a = __float2bfloat16(va), _b = __float2bfloat16(vb);     \
                stcg32(dhi + (off), packbf(_a, _b));                                    \
                stcg32(dlo + (off), packbf(__float2bfloat16((va) - __bfloat162float(_a)), \
                                           __float2bfloat16((vb) - __bfloat162float(_b)))); \
            } while (0)
            EMIT(o0,     h00, h01);
            EMIT(o1,     h10, h11);
            EMIT(o0 + 8, g00, g01);
            EMIT(o1 + 8, g10, g11);
            #undef EMIT
        }
        __syncthreads();

        if (tid == 0) {
            __threadfence();
            atomicExch(myflag, (unsigned)(t + 1));
        }
    }

    // final Dense(1): h_last = buffers[0]
    if (nq == 0) {
        if (tid < 16) {
            while (*(volatile unsigned*)&grpflags[tid * 16] < (unsigned)Tt) { }
        }
        __syncthreads();
        if (tid == 0) __threadfence();
        __syncthreads();
        const int brow = mbase + (tid >> 3);
        const int l = tid & 7;
        float s = 0.f;
        const __nv_bfloat16* hh = g_hhi[0] + (size_t)brow * Hh;
        const __nv_bfloat16* hl = g_hlo[0] + (size_t)brow * Hh;
        for (int k = l; k < Hh; k += 8) {
            float hv = __bfloat162float(__ldcg(&hh[k])) + __bfloat162float(__ldcg(&hl[k]));
            s += hv * __ldg(&Wfc[k]);
        }
        s += __shfl_down_sync(0xffffffffu, s, 4, 8);
        s += __shfl_down_sync(0xffffffffu, s, 2, 8);
        s += __shfl_down_sync(0xffffffffu, s, 1, 8);
        if (l == 0) out[brow] = s + __ldg(bfc) - 0.05f;
    }

    // exit: last CTA resets flag state for graph replay
    __syncthreads();
    if (tid == 0) {
        __threadfence();
        unsigned e = atomicAdd(&g_exit, 1u);
        if (e == (unsigned)(NCTA - 1)) {
            for (int i = 0; i < 8 * 16; i++) g_pflag[i * 16] = 0u;
            g_exit = 0u;
            __threadfence();
        }
    }
}

extern "C" void kernel_launch(void* const* d_in, const int* in_sizes, int n_in,
                              void* d_out, int out_size) {
    const float* x   = (const float*)d_in[0];
    const float* Wx  = (const float*)d_in[1];
    const float* Wh  = (const float*)d_in[2];
    const float* b   = (const float*)d_in[3];
    const float* Wfc = (const float*)d_in[4];
    const float* bfc = (const float*)d_in[5];
    float* out = (float*)d_out;
    (void)in_sizes; (void)n_in; (void)out_size;

    cudaFuncSetAttribute(xproj,   cudaFuncAttributeMaxDynamicSharedMemorySize, PK_SMEM);
    cudaFuncSetAttribute(rnn_mma, cudaFuncAttributeMaxDynamicSharedMemorySize, SM_DYN);
    xsplit<<<16384, 256>>>(x);
    xproj<<<16384, 256, PK_SMEM>>>(Wx);
    rnn_mma<<<NCTA, TPB, SM_DYN>>>(Wh, b, Wfc, bfc, out);
}